// round 13
// baseline (speedup 1.0000x reference)
#include <cuda_runtime.h>
#include <cuda_fp16.h>
#include <cstdint>

#define MAXN 100096
#define MAXE 1600000
#define DD 64

typedef unsigned long long ull;

// Scratch (allocation-free rule: __device__ globals; zero-init at load)
__device__ float  g_bufA[MAXN * DD];
__device__ float  g_bufB[MAXN * DD];
__device__ float  g_hin [MAXN * DD];
__device__ __half g_xh  [MAXN * DD];    // fp16 mirror (written by MLP epilogue)
__device__ int    g_off [MAXN + 1];
__device__ int    g_cur [MAXN];         // invariant: zero at kernel_launch entry
__device__ int    g_csr [MAXE];

// ---------------------------------------------------------------------------
// packed helpers
// ---------------------------------------------------------------------------
__device__ __forceinline__ uint32_t ph2(float a, float b) {
    __half2 h = __floats2half2_rn(a, b);
    return *(uint32_t*)&h;
}
__device__ __forceinline__ void acc_h8(uint4 v, float* a) {
    float2 f;
    f = __half22float2(*(__half2*)&v.x); a[0] += f.x; a[1] += f.y;
    f = __half22float2(*(__half2*)&v.y); a[2] += f.x; a[3] += f.y;
    f = __half22float2(*(__half2*)&v.z); a[4] += f.x; a[5] += f.y;
    f = __half22float2(*(__half2*)&v.w); a[6] += f.x; a[7] += f.y;
}
__device__ __forceinline__ void split_hl(float v, __half& h, __half& l) {
    h = __float2half_rn(v);
    l = __float2half_rn(v - __half2float(h));
}
__device__ __forceinline__ uint32_t packh(__half a, __half b) {
    __half2 t = __halves2half2(a, b);
    return *(uint32_t*)&t;
}
__device__ __forceinline__ void mma16816(
    float& c0, float& c1, float& c2, float& c3,
    uint32_t a0, uint32_t a1, uint32_t a2, uint32_t a3,
    uint32_t b0, uint32_t b1)
{
    asm volatile(
        "mma.sync.aligned.m16n8k16.row.col.f32.f16.f16.f32 "
        "{%0,%1,%2,%3},{%4,%5,%6,%7},{%8,%9},{%0,%1,%2,%3};"
        : "+f"(c0), "+f"(c1), "+f"(c2), "+f"(c3)
        : "r"(a0), "r"(a1), "r"(a2), "r"(a3), "r"(b0), "r"(b1));
}

// ---------------------------------------------------------------------------
// CSR build: hist -> single-kernel scan (redundant prefix) -> fill
// ---------------------------------------------------------------------------
__global__ void hist_kernel(const int* __restrict__ dst, int E,
                            int* __restrict__ deg) {
    int i = blockIdx.x * 256 + threadIdx.x;
    if (i < E) atomicAdd(&deg[__ldg(dst + i)], 1);
}

// One kernel, no cross-block dependency: each block redundantly computes the
// global prefix of its 256-node segment by summing deg[0..segStart), then does
// a local scan. Total redundant loads ~19.5M coalesced (~5us full-chip).
__global__ void __launch_bounds__(256) scan_one_kernel(
    int* __restrict__ cur,            // in: deg, out: running offsets
    int* __restrict__ off, int n, int E)
{
    __shared__ int ts[256];
    __shared__ int red[8];
    const int t = threadIdx.x;
    const int segStart = blockIdx.x * 256;

    // cooperative sum of deg[0..segStart)
    int pre = 0;
    for (int i = t; i < segStart; i += 256) pre += __ldg(cur + i);
    #pragma unroll
    for (int d = 16; d > 0; d >>= 1)
        pre += __shfl_down_sync(0xffffffffu, pre, d);
    if ((t & 31) == 0) red[t >> 5] = pre;
    __syncthreads();
    int sbase;
    {
        int v = (t < 8) ? red[t] : 0;
        #pragma unroll
        for (int d = 4; d > 0; d >>= 1)
            v += __shfl_down_sync(0xffffffffu, v, d);
        if (t == 0) red[0] = v;
        __syncthreads();
        sbase = red[0];
    }

    // local inclusive scan of this segment's 256 degrees
    int node = segStart + t;
    int v = (node < n) ? cur[node] : 0;
    ts[t] = v;
    __syncthreads();
    #pragma unroll
    for (int d = 1; d < 256; d <<= 1) {
        int u = (t >= d) ? ts[t - d] : 0;
        __syncthreads();
        ts[t] += u;
        __syncthreads();
    }
    if (node < n) {
        int o = sbase + ts[t] - v;    // exclusive
        off[node] = o;
        cur[node] = o;
    }
    if (segStart == 0 && t == 0) off[n] = E;
}

__global__ void fill_kernel(const int* __restrict__ src,
                            const int* __restrict__ dst, int E,
                            int* __restrict__ cur, int* __restrict__ csr) {
    int i = blockIdx.x * 256 + threadIdx.x;
    if (i < E) {
        int d = __ldg(dst + i);
        int p = atomicAdd(&cur[d], 1);
        csr[p] = __ldg(src + i);
    }
}

__global__ void zero_cur_kernel(int* __restrict__ cur, int n) {
    int i = blockIdx.x * 256 + threadIdx.x;
    if (i < n) cur[i] = 0;            // restore invariant for next call
}

// ---------------------------------------------------------------------------
// Gather: hin[i] = (1+eps)*x[i](fp32) + sum_{j in N_in(i)} nbr[j]
//   USE16=true : neighbors from fp16 mirror (layers 2,3)
//   USE16=false: neighbors from fp32 x (layer 1; no x2h needed, exact)
// 8 lanes per node; unroll 8 neighbors for more loads in flight.
// ---------------------------------------------------------------------------
template<bool USE16>
__global__ void __launch_bounds__(256) gather_kernel(
    const float*  __restrict__ x,
    const __half* __restrict__ xh,
    const int*    __restrict__ off,
    const int*    __restrict__ csr,
    const float*  __restrict__ eps, int l,
    float*        __restrict__ out, int n)
{
    int idx = blockIdx.x * 256 + threadIdx.x;
    int node = idx >> 3;
    if (node >= n) return;
    int c = idx & 7;

    const uint4*  XH = (const uint4*)xh;
    const float4* X4 = (const float4*)x;
    float e1 = 1.0f + __ldg(eps + l);

    float a[8];
    {
        float4 s0 = __ldg(X4 + (size_t)node * 16 + 2 * c);
        float4 s1 = __ldg(X4 + (size_t)node * 16 + 2 * c + 1);
        a[0] = e1 * s0.x; a[1] = e1 * s0.y; a[2] = e1 * s0.z; a[3] = e1 * s0.w;
        a[4] = e1 * s1.x; a[5] = e1 * s1.y; a[6] = e1 * s1.z; a[7] = e1 * s1.w;
    }

    int beg = __ldg(off + node);
    int end = __ldg(off + node + 1);
    int j = beg;
    for (; j + 7 < end; j += 8) {
        int nb[8];
        #pragma unroll
        for (int u = 0; u < 8; u++) nb[u] = __ldg(csr + j + u);
        if (USE16) {
            uint4 v[8];
            #pragma unroll
            for (int u = 0; u < 8; u++) v[u] = __ldg(XH + (size_t)nb[u] * 8 + c);
            #pragma unroll
            for (int u = 0; u < 8; u++) acc_h8(v[u], a);
        } else {
            #pragma unroll
            for (int u = 0; u < 8; u++) {
                float4 p = __ldg(X4 + (size_t)nb[u] * 16 + 2 * c);
                float4 q = __ldg(X4 + (size_t)nb[u] * 16 + 2 * c + 1);
                a[0] += p.x; a[1] += p.y; a[2] += p.z; a[3] += p.w;
                a[4] += q.x; a[5] += q.y; a[6] += q.z; a[7] += q.w;
            }
        }
    }
    for (; j + 3 < end; j += 4) {
        int nb[4];
        #pragma unroll
        for (int u = 0; u < 4; u++) nb[u] = __ldg(csr + j + u);
        if (USE16) {
            uint4 v[4];
            #pragma unroll
            for (int u = 0; u < 4; u++) v[u] = __ldg(XH + (size_t)nb[u] * 8 + c);
            #pragma unroll
            for (int u = 0; u < 4; u++) acc_h8(v[u], a);
        } else {
            #pragma unroll
            for (int u = 0; u < 4; u++) {
                float4 p = __ldg(X4 + (size_t)nb[u] * 16 + 2 * c);
                float4 q = __ldg(X4 + (size_t)nb[u] * 16 + 2 * c + 1);
                a[0] += p.x; a[1] += p.y; a[2] += p.z; a[3] += p.w;
                a[4] += q.x; a[5] += q.y; a[6] += q.z; a[7] += q.w;
            }
        }
    }
    for (; j < end; j++) {
        int nb = __ldg(csr + j);
        if (USE16) {
            acc_h8(__ldg(XH + (size_t)nb * 8 + c), a);
        } else {
            float4 p = __ldg(X4 + (size_t)nb * 16 + 2 * c);
            float4 q = __ldg(X4 + (size_t)nb * 16 + 2 * c + 1);
            a[0] += p.x; a[1] += p.y; a[2] += p.z; a[3] += p.w;
            a[4] += q.x; a[5] += q.y; a[6] += q.z; a[7] += q.w;
        }
    }

    float4* o = (float4*)out + (size_t)node * 16 + 2 * c;
    o[0] = make_float4(a[0], a[1], a[2], a[3]);
    o[1] = make_float4(a[4], a[5], a[6], a[7]);
}

// ---------------------------------------------------------------------------
// Tensor-core GIN MLP.  (R12-proven, unchanged)
// ---------------------------------------------------------------------------
#define AST   72
#define W1HI  0
#define W1LO  4608
#define W2HI  9216
#define W2LO  13824
#define A_HI  18432
#define A_LO  27648
#define H_TOT 36864
#define MLP_SMEM_BYTES (H_TOT * 2 + 128 * 4)

__global__ void __launch_bounds__(256, 2) gin_mlp_kernel(
    const float* __restrict__ hin,
    const float* __restrict__ W1g, const float* __restrict__ b1g,
    const float* __restrict__ W2g, const float* __restrict__ b2g,
    int l, float* __restrict__ xout, __half* __restrict__ xh,
    int n, int nTiles)
{
    extern __shared__ __half smh[];
    float* fb = (float*)(smh + H_TOT);
    const int tid  = threadIdx.x;
    const int warp = tid >> 5;
    const int lane = tid & 31;
    const int g    = lane >> 2;
    const int t    = lane & 3;

    for (int e = tid; e < 4096; e += 256) {
        int k = e >> 6, nn = e & 63;
        float w1 = __ldg(W1g + (size_t)l * 4096 + e);
        float w2 = __ldg(W2g + (size_t)l * 4096 + e);
        __half h, lo;
        split_hl(w1, h, lo);
        smh[W1HI + nn * AST + k] = h;  smh[W1LO + nn * AST + k] = lo;
        split_hl(w2, h, lo);
        smh[W2HI + nn * AST + k] = h;  smh[W2LO + nn * AST + k] = lo;
    }
    if (tid < 64)       fb[tid] = __ldg(b1g + l * 64 + tid);
    else if (tid < 128) fb[tid] = __ldg(b2g + l * 64 + (tid - 64));
    __syncthreads();

    __half* Ah = smh + A_HI + warp * (16 * AST);
    __half* Al = smh + A_LO + warp * (16 * AST);

    for (int tile = blockIdx.x; tile < nTiles; tile += gridDim.x) {
        const int rowBase = tile * 128 + warp * 16;

        __syncwarp();
        {
            const float4* gsrc = (const float4*)hin + (size_t)rowBase * 16;
            #pragma unroll
            for (int i = 0; i < 8; i++) {
                int idx = i * 32 + lane;
                float4 v = __ldg(gsrc + idx);
                int r = idx >> 4, c4 = idx & 15;
                __half h0,l0,h1,l1,h2v,l2,h3,l3;
                split_hl(v.x, h0, l0); split_hl(v.y, h1, l1);
                split_hl(v.z, h2v, l2); split_hl(v.w, h3, l3);
                uint2 hh; hh.x = packh(h0, h1); hh.y = packh(h2v, h3);
                uint2 ll; ll.x = packh(l0, l1); ll.y = packh(l2, l3);
                *(uint2*)(Ah + r * AST + c4 * 4) = hh;
                *(uint2*)(Al + r * AST + c4 * 4) = ll;
            }
        }
        __syncwarp();

        uint32_t ah0[4], ah1[4], ah2[4], ah3[4];
        uint32_t al0[4], al1[4], al2[4], al3[4];
        #pragma unroll
        for (int kc = 0; kc < 4; kc++) {
            int o0 = g * AST + kc * 16 + 2 * t;
            int o1 = (g + 8) * AST + kc * 16 + 2 * t;
            ah0[kc] = *(const uint32_t*)(Ah + o0);
            ah1[kc] = *(const uint32_t*)(Ah + o1);
            ah2[kc] = *(const uint32_t*)(Ah + o0 + 8);
            ah3[kc] = *(const uint32_t*)(Ah + o1 + 8);
            al0[kc] = *(const uint32_t*)(Al + o0);
            al1[kc] = *(const uint32_t*)(Al + o1);
            al2[kc] = *(const uint32_t*)(Al + o0 + 8);
            al3[kc] = *(const uint32_t*)(Al + o1 + 8);
        }

        float hc[8][4];
        #pragma unroll
        for (int nc = 0; nc < 8; nc++) {
            float b0 = fb[nc * 8 + 2 * t], b1v = fb[nc * 8 + 2 * t + 1];
            float c0 = b0, c1 = b1v, c2 = b0, c3 = b1v;
            #pragma unroll
            for (int kc = 0; kc < 4; kc++) {
                const __half* ph = smh + W1HI + (nc * 8 + g) * AST + kc * 16 + 2 * t;
                const __half* pl = smh + W1LO + (nc * 8 + g) * AST + kc * 16 + 2 * t;
                uint32_t bh0 = *(const uint32_t*)ph;
                uint32_t bh1 = *(const uint32_t*)(ph + 8);
                uint32_t bl0 = *(const uint32_t*)pl;
                uint32_t bl1 = *(const uint32_t*)(pl + 8);
                mma16816(c0,c1,c2,c3, ah0[kc],ah1[kc],ah2[kc],ah3[kc], bh0,bh1);
                mma16816(c0,c1,c2,c3, al0[kc],al1[kc],al2[kc],al3[kc], bh0,bh1);
                mma16816(c0,c1,c2,c3, ah0[kc],ah1[kc],ah2[kc],ah3[kc], bl0,bl1);
            }
            hc[nc][0] = c0; hc[nc][1] = c1; hc[nc][2] = c2; hc[nc][3] = c3;
        }

        uint32_t bh0a[4], bh1a[4], bh2a[4], bh3a[4];
        uint32_t bl0a[4], bl1a[4], bl2a[4], bl3a[4];
        #pragma unroll
        for (int kc = 0; kc < 4; kc++) {
            float r00 = fmaxf(hc[2*kc][0], 0.f), r01 = fmaxf(hc[2*kc][1], 0.f);
            float r02 = fmaxf(hc[2*kc][2], 0.f), r03 = fmaxf(hc[2*kc][3], 0.f);
            float r10 = fmaxf(hc[2*kc+1][0], 0.f), r11 = fmaxf(hc[2*kc+1][1], 0.f);
            float r12 = fmaxf(hc[2*kc+1][2], 0.f), r13 = fmaxf(hc[2*kc+1][3], 0.f);
            __half h0,l0,h1,l1;
            split_hl(r00,h0,l0); split_hl(r01,h1,l1);
            bh0a[kc] = packh(h0,h1); bl0a[kc] = packh(l0,l1);
            split_hl(r02,h0,l0); split_hl(r03,h1,l1);
            bh1a[kc] = packh(h0,h1); bl1a[kc] = packh(l0,l1);
            split_hl(r10,h0,l0); split_hl(r11,h1,l1);
            bh2a[kc] = packh(h0,h1); bl2a[kc] = packh(l0,l1);
            split_hl(r12,h0,l0); split_hl(r13,h1,l1);
            bh3a[kc] = packh(h0,h1); bl3a[kc] = packh(l0,l1);
        }

        #pragma unroll
        for (int nc = 0; nc < 8; nc++) {
            float b0 = fb[64 + nc * 8 + 2 * t], b1v = fb[64 + nc * 8 + 2 * t + 1];
            float c0 = b0, c1 = b1v, c2 = b0, c3 = b1v;
            #pragma unroll
            for (int kc = 0; kc < 4; kc++) {
                const __half* ph = smh + W2HI + (nc * 8 + g) * AST + kc * 16 + 2 * t;
                const __half* pl = smh + W2LO + (nc * 8 + g) * AST + kc * 16 + 2 * t;
                uint32_t wh0 = *(const uint32_t*)ph;
                uint32_t wh1 = *(const uint32_t*)(ph + 8);
                uint32_t wl0 = *(const uint32_t*)pl;
                uint32_t wl1 = *(const uint32_t*)(pl + 8);
                mma16816(c0,c1,c2,c3, bh0a[kc],bh1a[kc],bh2a[kc],bh3a[kc], wh0,wh1);
                mma16816(c0,c1,c2,c3, bl0a[kc],bl1a[kc],bl2a[kc],bl3a[kc], wh0,wh1);
                mma16816(c0,c1,c2,c3, bh0a[kc],bh1a[kc],bh2a[kc],bh3a[kc], wl0,wl1);
            }
            float f0 = fmaxf(c0, 0.f), f1 = fmaxf(c1, 0.f);
            float f2 = fmaxf(c2, 0.f), f3 = fmaxf(c3, 0.f);
            int col  = nc * 8 + 2 * t;
            int row0 = rowBase + g;
            int row1 = row0 + 8;
            if (row0 < n) {
                *(float2*)(xout + (size_t)row0 * DD + col) = make_float2(f0, f1);
                *(uint32_t*)(xh + (size_t)row0 * DD + col) = ph2(f0, f1);
            }
            if (row1 < n) {
                *(float2*)(xout + (size_t)row1 * DD + col) = make_float2(f2, f3);
                *(uint32_t*)(xh + (size_t)row1 * DD + col) = ph2(f2, f3);
            }
        }
    }
}

// ---------------------------------------------------------------------------
// Final projection on tensor cores: out = x @ Wf + bf (no relu), compensated.
// SMEM (halves): Wfhi/Wflo 2x4608 | Ahi/Alo 8 warps x 1152 each  + 64 floats.
// ---------------------------------------------------------------------------
#define FWHI  0
#define FWLO  4608
#define FA_HI 9216
#define FA_LO 18432
#define F_TOT 27648
#define FIN_SMEM_BYTES (F_TOT * 2 + 64 * 4)

__global__ void __launch_bounds__(256, 2) final_mma_kernel(
    const float* __restrict__ xin,
    const float* __restrict__ Wfg, const float* __restrict__ bfg,
    float* __restrict__ out, int n, int nTiles)
{
    extern __shared__ __half smh[];
    float* fb = (float*)(smh + F_TOT);
    const int tid  = threadIdx.x;
    const int warp = tid >> 5;
    const int lane = tid & 31;
    const int g    = lane >> 2;
    const int t    = lane & 3;

    for (int e = tid; e < 4096; e += 256) {
        int k = e >> 6, nn = e & 63;
        float w = __ldg(Wfg + e);
        __half h, lo;
        split_hl(w, h, lo);
        smh[FWHI + nn * AST + k] = h;  smh[FWLO + nn * AST + k] = lo;
    }
    if (tid < 64) fb[tid] = __ldg(bfg + tid);
    __syncthreads();

    __half* Ah = smh + FA_HI + warp * (16 * AST);
    __half* Al = smh + FA_LO + warp * (16 * AST);

    for (int tile = blockIdx.x; tile < nTiles; tile += gridDim.x) {
        const int rowBase = tile * 128 + warp * 16;

        __syncwarp();
        {
            const float4* gsrc = (const float4*)xin + (size_t)rowBase * 16;
            #pragma unroll
            for (int i = 0; i < 8; i++) {
                int idx = i * 32 + lane;
                float4 v = __ldg(gsrc + idx);
                int r = idx >> 4, c4 = idx & 15;
                __half h0,l0,h1,l1,h2v,l2,h3,l3;
                split_hl(v.x, h0, l0); split_hl(v.y, h1, l1);
                split_hl(v.z, h2v, l2); split_hl(v.w, h3, l3);
                uint2 hh; hh.x = packh(h0, h1); hh.y = packh(h2v, h3);
                uint2 ll; ll.x = packh(l0, l1); ll.y = packh(l2, l3);
                *(uint2*)(Ah + r * AST + c4 * 4) = hh;
                *(uint2*)(Al + r * AST + c4 * 4) = ll;
            }
        }
        __syncwarp();

        uint32_t ah0[4], ah1[4], ah2[4], ah3[4];
        uint32_t al0[4], al1[4], al2[4], al3[4];
        #pragma unroll
        for (int kc = 0; kc < 4; kc++) {
            int o0 = g * AST + kc * 16 + 2 * t;
            int o1 = (g + 8) * AST + kc * 16 + 2 * t;
            ah0[kc] = *(const uint32_t*)(Ah + o0);
            ah1[kc] = *(const uint32_t*)(Ah + o1);
            ah2[kc] = *(const uint32_t*)(Ah + o0 + 8);
            ah3[kc] = *(const uint32_t*)(Ah + o1 + 8);
            al0[kc] = *(const uint32_t*)(Al + o0);
            al1[kc] = *(const uint32_t*)(Al + o1);
            al2[kc] = *(const uint32_t*)(Al + o0 + 8);
            al3[kc] = *(const uint32_t*)(Al + o1 + 8);
        }

        #pragma unroll
        for (int nc = 0; nc < 8; nc++) {
            float b0 = fb[nc * 8 + 2 * t], b1v = fb[nc * 8 + 2 * t + 1];
            float c0 = b0, c1 = b1v, c2 = b0, c3 = b1v;
            #pragma unroll
            for (int kc = 0; kc < 4; kc++) {
                const __half* ph = smh + FWHI + (nc * 8 + g) * AST + kc * 16 + 2 * t;
                const __half* pl = smh + FWLO + (nc * 8 + g) * AST + kc * 16 + 2 * t;
                uint32_t bh0 = *(const uint32_t*)ph;
                uint32_t bh1 = *(const uint32_t*)(ph + 8);
                uint32_t bl0 = *(const uint32_t*)pl;
                uint32_t bl1 = *(const uint32_t*)(pl + 8);
                mma16816(c0,c1,c2,c3, ah0[kc],ah1[kc],ah2[kc],ah3[kc], bh0,bh1);
                mma16816(c0,c1,c2,c3, al0[kc],al1[kc],al2[kc],al3[kc], bh0,bh1);
                mma16816(c0,c1,c2,c3, ah0[kc],ah1[kc],ah2[kc],ah3[kc], bl0,bl1);
            }
            int col  = nc * 8 + 2 * t;
            int row0 = rowBase + g;
            int row1 = row0 + 8;
            if (row0 < n)
                *(float2*)(out + (size_t)row0 * DD + col) = make_float2(c0, c1);
            if (row1 < n)
                *(float2*)(out + (size_t)row1 * DD + col) = make_float2(c2, c3);
        }
    }
}

// ---------------------------------------------------------------------------
// Launch: hist -> scan_one -> fill -> 3 x (gather; MLP) -> final -> restore.
// Graph-capturable, allocation-free, deterministic.
// ---------------------------------------------------------------------------
extern "C" void kernel_launch(void* const* d_in, const int* in_sizes, int n_in,
                              void* d_out, int out_size)
{
    const float* x   = (const float*)d_in[0];
    const int*   ei  = (const int*)  d_in[1];
    const float* W1  = (const float*)d_in[2];
    const float* b1  = (const float*)d_in[3];
    const float* W2  = (const float*)d_in[4];
    const float* b2  = (const float*)d_in[5];
    const float* eps = (const float*)d_in[6];
    const float* Wf  = (const float*)d_in[7];
    const float* bf  = (const float*)d_in[8];

    const int n = in_sizes[0] / DD;
    const int E = in_sizes[1] / 2;
    const int* src = ei;
    const int* dst = ei + E;

    float *bufA, *bufB, *hin;
    __half* xh;
    int *off, *cur, *csr;
    cudaGetSymbolAddress((void**)&bufA, g_bufA);
    cudaGetSymbolAddress((void**)&bufB, g_bufB);
    cudaGetSymbolAddress((void**)&hin,  g_hin);
    cudaGetSymbolAddress((void**)&xh,   g_xh);
    cudaGetSymbolAddress((void**)&off,  g_off);
    cudaGetSymbolAddress((void**)&cur,  g_cur);
    cudaGetSymbolAddress((void**)&csr,  g_csr);

    cudaFuncSetAttribute(gin_mlp_kernel,
                         cudaFuncAttributeMaxDynamicSharedMemorySize,
                         MLP_SMEM_BYTES);
    cudaFuncSetAttribute(final_mma_kernel,
                         cudaFuncAttributeMaxDynamicSharedMemorySize,
                         FIN_SMEM_BYTES);

    // ---- CSR build (cur is zero on entry; restored at end)
    hist_kernel<<<(E + 255) / 256, 256>>>(dst, E, cur);
    scan_one_kernel<<<(n + 255) / 256, 256>>>(cur, off, n, E);
    fill_kernel<<<(E + 255) / 256, 256>>>(src, dst, E, cur, csr);

    // ---- Layers
    const int gatherBlocks = (n * 8 + 255) / 256;
    const int mlpTiles = (n + 127) / 128;
    int mlpGrid = 296;                        // 2 blocks x 148 SMs
    if (mlpGrid > mlpTiles) mlpGrid = mlpTiles;

    const float* curx = x;
    float*       nxt  = bufA;
    for (int l = 0; l < 3; l++) {
        if (l == 0)
            gather_kernel<false><<<gatherBlocks, 256>>>(
                curx, xh, off, csr, eps, l, hin, n);
        else
            gather_kernel<true><<<gatherBlocks, 256>>>(
                curx, xh, off, csr, eps, l, hin, n);
        gin_mlp_kernel<<<mlpGrid, 256, MLP_SMEM_BYTES>>>(
            hin, W1, b1, W2, b2, l, nxt, xh, n, mlpTiles);
        curx = nxt;
        nxt = (curx == bufA) ? bufB : bufA;
    }

    final_mma_kernel<<<mlpGrid, 256, FIN_SMEM_BYTES>>>(
        curx, Wf, bf, (float*)d_out, n, mlpTiles);

    // ---- restore cur = 0 for the next call
    zero_cur_kernel<<<(n + 255) / 256, 256>>>(cur, n);
}

// round 14
// speedup vs baseline: 1.0326x; 1.0326x over previous
#include <cuda_runtime.h>
#include <cuda_fp16.h>
#include <cstdint>

#define MAXN 100096
#define MAXE 1600000
#define DD 64

typedef unsigned long long ull;

// Scratch (allocation-free rule: __device__ globals; zero-init at load)
__device__ float  g_bufA[MAXN * DD];
__device__ float  g_bufB[MAXN * DD];
__device__ float  g_hin [MAXN * DD];
__device__ __half g_xh  [MAXN * DD];    // fp16 mirror of current x
__device__ int    g_off [MAXN + 1];
__device__ int    g_cur [MAXN];         // invariant: zero at kernel_launch entry
__device__ int    g_csr [MAXE];

// ---------------------------------------------------------------------------
// packed helpers
// ---------------------------------------------------------------------------
__device__ __forceinline__ uint32_t ph2(float a, float b) {
    __half2 h = __floats2half2_rn(a, b);
    return *(uint32_t*)&h;
}
__device__ __forceinline__ void acc_h8(uint4 v, float* a) {
    float2 f;
    f = __half22float2(*(__half2*)&v.x); a[0] += f.x; a[1] += f.y;
    f = __half22float2(*(__half2*)&v.y); a[2] += f.x; a[3] += f.y;
    f = __half22float2(*(__half2*)&v.z); a[4] += f.x; a[5] += f.y;
    f = __half22float2(*(__half2*)&v.w); a[6] += f.x; a[7] += f.y;
}
__device__ __forceinline__ void split_hl(float v, __half& h, __half& l) {
    h = __float2half_rn(v);
    l = __float2half_rn(v - __half2float(h));
}
__device__ __forceinline__ uint32_t packh(__half a, __half b) {
    __half2 t = __halves2half2(a, b);
    return *(uint32_t*)&t;
}
__device__ __forceinline__ void mma16816(
    float& c0, float& c1, float& c2, float& c3,
    uint32_t a0, uint32_t a1, uint32_t a2, uint32_t a3,
    uint32_t b0, uint32_t b1)
{
    asm volatile(
        "mma.sync.aligned.m16n8k16.row.col.f32.f16.f16.f32 "
        "{%0,%1,%2,%3},{%4,%5,%6,%7},{%8,%9},{%0,%1,%2,%3};"
        : "+f"(c0), "+f"(c1), "+f"(c2), "+f"(c3)
        : "r"(a0), "r"(a1), "r"(a2), "r"(a3), "r"(b0), "r"(b1));
}

// ---------------------------------------------------------------------------
// CSR build: hist (int4) -> single-kernel scan -> fill (int4)
// ---------------------------------------------------------------------------
__global__ void hist_kernel(const int* __restrict__ dst, int E,
                            int* __restrict__ deg) {
    int i = blockIdx.x * 256 + threadIdx.x;      // quad index
    int base = i * 4;
    if (base + 3 < E) {
        int4 d = __ldg((const int4*)dst + i);
        atomicAdd(&deg[d.x], 1);
        atomicAdd(&deg[d.y], 1);
        atomicAdd(&deg[d.z], 1);
        atomicAdd(&deg[d.w], 1);
    } else {
        for (int e = base; e < E; e++)
            atomicAdd(&deg[__ldg(dst + e)], 1);
    }
}

// One kernel, no cross-block dependency: each block redundantly computes the
// global prefix of its 256-node segment, then a local scan.
__global__ void __launch_bounds__(256) scan_one_kernel(
    int* __restrict__ cur,            // in: deg, out: running offsets
    int* __restrict__ off, int n, int E)
{
    __shared__ int ts[256];
    __shared__ int red[8];
    const int t = threadIdx.x;
    const int segStart = blockIdx.x * 256;

    int pre = 0;
    for (int i = t; i < segStart; i += 256) pre += __ldg(cur + i);
    #pragma unroll
    for (int d = 16; d > 0; d >>= 1)
        pre += __shfl_down_sync(0xffffffffu, pre, d);
    if ((t & 31) == 0) red[t >> 5] = pre;
    __syncthreads();
    int sbase;
    {
        int v = (t < 8) ? red[t] : 0;
        #pragma unroll
        for (int d = 4; d > 0; d >>= 1)
            v += __shfl_down_sync(0xffffffffu, v, d);
        if (t == 0) red[0] = v;
        __syncthreads();
        sbase = red[0];
    }

    int node = segStart + t;
    int v = (node < n) ? cur[node] : 0;
    ts[t] = v;
    __syncthreads();
    #pragma unroll
    for (int d = 1; d < 256; d <<= 1) {
        int u = (t >= d) ? ts[t - d] : 0;
        __syncthreads();
        ts[t] += u;
        __syncthreads();
    }
    if (node < n) {
        int o = sbase + ts[t] - v;    // exclusive
        off[node] = o;
        cur[node] = o;
    }
    if (segStart == 0 && t == 0) off[n] = E;
}

__global__ void fill_kernel(const int* __restrict__ src,
                            const int* __restrict__ dst, int E,
                            int* __restrict__ cur, int* __restrict__ csr) {
    int i = blockIdx.x * 256 + threadIdx.x;      // quad index
    int base = i * 4;
    if (base + 3 < E) {
        int4 d = __ldg((const int4*)dst + i);
        int4 s = __ldg((const int4*)src + i);
        int p0 = atomicAdd(&cur[d.x], 1);
        int p1 = atomicAdd(&cur[d.y], 1);
        int p2 = atomicAdd(&cur[d.z], 1);
        int p3 = atomicAdd(&cur[d.w], 1);
        csr[p0] = s.x; csr[p1] = s.y; csr[p2] = s.z; csr[p3] = s.w;
    } else {
        for (int e = base; e < E; e++) {
            int d = __ldg(dst + e);
            int p = atomicAdd(&cur[d], 1);
            csr[p] = __ldg(src + e);
        }
    }
}

__global__ void zero_cur_kernel(int* __restrict__ cur, int n) {
    int i = blockIdx.x * 256 + threadIdx.x;
    if (i < n) cur[i] = 0;            // restore invariant for next call
}

// ---------------------------------------------------------------------------
// fp32 -> fp16 mirror of the input x (once per call)
// ---------------------------------------------------------------------------
__global__ void x2h_kernel(const float* __restrict__ x,
                           __half* __restrict__ xh, int total4) {
    int i = blockIdx.x * 256 + threadIdx.x;
    if (i < total4) {
        float4 v = __ldg((const float4*)x + i);
        uint2 u;
        u.x = ph2(v.x, v.y);
        u.y = ph2(v.z, v.w);
        ((uint2*)xh)[i] = u;
    }
}

// ---------------------------------------------------------------------------
// Gather: hin[i] = (1+eps)*x[i](fp32) + sum_{j in N_in(i)} xh[j](fp16)
// 8 lanes per node, uint4 fp16 neighbor loads: ONE 128B line per edge-row,
// the minimum possible L1 wavefront count.  Unroll 8.
// ---------------------------------------------------------------------------
__global__ void __launch_bounds__(256) gather_kernel(
    const float*  __restrict__ x,
    const __half* __restrict__ xh,
    const int*    __restrict__ off,
    const int*    __restrict__ csr,
    const float*  __restrict__ eps, int l,
    float*        __restrict__ out, int n)
{
    int idx = blockIdx.x * 256 + threadIdx.x;
    int node = idx >> 3;
    if (node >= n) return;
    int c = idx & 7;

    const uint4*  XH = (const uint4*)xh;
    const float4* X4 = (const float4*)x;
    float e1 = 1.0f + __ldg(eps + l);

    float a[8];
    {
        float4 s0 = __ldg(X4 + (size_t)node * 16 + 2 * c);
        float4 s1 = __ldg(X4 + (size_t)node * 16 + 2 * c + 1);
        a[0] = e1 * s0.x; a[1] = e1 * s0.y; a[2] = e1 * s0.z; a[3] = e1 * s0.w;
        a[4] = e1 * s1.x; a[5] = e1 * s1.y; a[6] = e1 * s1.z; a[7] = e1 * s1.w;
    }

    int beg = __ldg(off + node);
    int end = __ldg(off + node + 1);
    int j = beg;
    for (; j + 7 < end; j += 8) {
        int nb[8];
        #pragma unroll
        for (int u = 0; u < 8; u++) nb[u] = __ldg(csr + j + u);
        uint4 v[8];
        #pragma unroll
        for (int u = 0; u < 8; u++) v[u] = __ldg(XH + (size_t)nb[u] * 8 + c);
        #pragma unroll
        for (int u = 0; u < 8; u++) acc_h8(v[u], a);
    }
    for (; j + 3 < end; j += 4) {
        int nb[4];
        #pragma unroll
        for (int u = 0; u < 4; u++) nb[u] = __ldg(csr + j + u);
        uint4 v[4];
        #pragma unroll
        for (int u = 0; u < 4; u++) v[u] = __ldg(XH + (size_t)nb[u] * 8 + c);
        #pragma unroll
        for (int u = 0; u < 4; u++) acc_h8(v[u], a);
    }
    for (; j < end; j++)
        acc_h8(__ldg(XH + (size_t)__ldg(csr + j) * 8 + c), a);

    float4* o = (float4*)out + (size_t)node * 16 + 2 * c;
    o[0] = make_float4(a[0], a[1], a[2], a[3]);
    o[1] = make_float4(a[4], a[5], a[6], a[7]);
}

// ---------------------------------------------------------------------------
// Tensor-core GIN MLP.  (R12-proven, unchanged)
// ---------------------------------------------------------------------------
#define AST   72
#define W1HI  0
#define W1LO  4608
#define W2HI  9216
#define W2LO  13824
#define A_HI  18432
#define A_LO  27648
#define H_TOT 36864
#define MLP_SMEM_BYTES (H_TOT * 2 + 128 * 4)

__global__ void __launch_bounds__(256, 2) gin_mlp_kernel(
    const float* __restrict__ hin,
    const float* __restrict__ W1g, const float* __restrict__ b1g,
    const float* __restrict__ W2g, const float* __restrict__ b2g,
    int l, float* __restrict__ xout, __half* __restrict__ xh,
    int n, int nTiles)
{
    extern __shared__ __half smh[];
    float* fb = (float*)(smh + H_TOT);
    const int tid  = threadIdx.x;
    const int warp = tid >> 5;
    const int lane = tid & 31;
    const int g    = lane >> 2;
    const int t    = lane & 3;

    for (int e = tid; e < 4096; e += 256) {
        int k = e >> 6, nn = e & 63;
        float w1 = __ldg(W1g + (size_t)l * 4096 + e);
        float w2 = __ldg(W2g + (size_t)l * 4096 + e);
        __half h, lo;
        split_hl(w1, h, lo);
        smh[W1HI + nn * AST + k] = h;  smh[W1LO + nn * AST + k] = lo;
        split_hl(w2, h, lo);
        smh[W2HI + nn * AST + k] = h;  smh[W2LO + nn * AST + k] = lo;
    }
    if (tid < 64)       fb[tid] = __ldg(b1g + l * 64 + tid);
    else if (tid < 128) fb[tid] = __ldg(b2g + l * 64 + (tid - 64));
    __syncthreads();

    __half* Ah = smh + A_HI + warp * (16 * AST);
    __half* Al = smh + A_LO + warp * (16 * AST);

    for (int tile = blockIdx.x; tile < nTiles; tile += gridDim.x) {
        const int rowBase = tile * 128 + warp * 16;

        __syncwarp();
        {
            const float4* gsrc = (const float4*)hin + (size_t)rowBase * 16;
            #pragma unroll
            for (int i = 0; i < 8; i++) {
                int idx = i * 32 + lane;
                float4 v = __ldg(gsrc + idx);
                int r = idx >> 4, c4 = idx & 15;
                __half h0,l0,h1,l1,h2v,l2,h3,l3;
                split_hl(v.x, h0, l0); split_hl(v.y, h1, l1);
                split_hl(v.z, h2v, l2); split_hl(v.w, h3, l3);
                uint2 hh; hh.x = packh(h0, h1); hh.y = packh(h2v, h3);
                uint2 ll; ll.x = packh(l0, l1); ll.y = packh(l2, l3);
                *(uint2*)(Ah + r * AST + c4 * 4) = hh;
                *(uint2*)(Al + r * AST + c4 * 4) = ll;
            }
        }
        __syncwarp();

        uint32_t ah0[4], ah1[4], ah2[4], ah3[4];
        uint32_t al0[4], al1[4], al2[4], al3[4];
        #pragma unroll
        for (int kc = 0; kc < 4; kc++) {
            int o0 = g * AST + kc * 16 + 2 * t;
            int o1 = (g + 8) * AST + kc * 16 + 2 * t;
            ah0[kc] = *(const uint32_t*)(Ah + o0);
            ah1[kc] = *(const uint32_t*)(Ah + o1);
            ah2[kc] = *(const uint32_t*)(Ah + o0 + 8);
            ah3[kc] = *(const uint32_t*)(Ah + o1 + 8);
            al0[kc] = *(const uint32_t*)(Al + o0);
            al1[kc] = *(const uint32_t*)(Al + o1);
            al2[kc] = *(const uint32_t*)(Al + o0 + 8);
            al3[kc] = *(const uint32_t*)(Al + o1 + 8);
        }

        float hc[8][4];
        #pragma unroll
        for (int nc = 0; nc < 8; nc++) {
            float b0 = fb[nc * 8 + 2 * t], b1v = fb[nc * 8 + 2 * t + 1];
            float c0 = b0, c1 = b1v, c2 = b0, c3 = b1v;
            #pragma unroll
            for (int kc = 0; kc < 4; kc++) {
                const __half* ph = smh + W1HI + (nc * 8 + g) * AST + kc * 16 + 2 * t;
                const __half* pl = smh + W1LO + (nc * 8 + g) * AST + kc * 16 + 2 * t;
                uint32_t bh0 = *(const uint32_t*)ph;
                uint32_t bh1 = *(const uint32_t*)(ph + 8);
                uint32_t bl0 = *(const uint32_t*)pl;
                uint32_t bl1 = *(const uint32_t*)(pl + 8);
                mma16816(c0,c1,c2,c3, ah0[kc],ah1[kc],ah2[kc],ah3[kc], bh0,bh1);
                mma16816(c0,c1,c2,c3, al0[kc],al1[kc],al2[kc],al3[kc], bh0,bh1);
                mma16816(c0,c1,c2,c3, ah0[kc],ah1[kc],ah2[kc],ah3[kc], bl0,bl1);
            }
            hc[nc][0] = c0; hc[nc][1] = c1; hc[nc][2] = c2; hc[nc][3] = c3;
        }

        uint32_t bh0a[4], bh1a[4], bh2a[4], bh3a[4];
        uint32_t bl0a[4], bl1a[4], bl2a[4], bl3a[4];
        #pragma unroll
        for (int kc = 0; kc < 4; kc++) {
            float r00 = fmaxf(hc[2*kc][0], 0.f), r01 = fmaxf(hc[2*kc][1], 0.f);
            float r02 = fmaxf(hc[2*kc][2], 0.f), r03 = fmaxf(hc[2*kc][3], 0.f);
            float r10 = fmaxf(hc[2*kc+1][0], 0.f), r11 = fmaxf(hc[2*kc+1][1], 0.f);
            float r12 = fmaxf(hc[2*kc+1][2], 0.f), r13 = fmaxf(hc[2*kc+1][3], 0.f);
            __half h0,l0,h1,l1;
            split_hl(r00,h0,l0); split_hl(r01,h1,l1);
            bh0a[kc] = packh(h0,h1); bl0a[kc] = packh(l0,l1);
            split_hl(r02,h0,l0); split_hl(r03,h1,l1);
            bh1a[kc] = packh(h0,h1); bl1a[kc] = packh(l0,l1);
            split_hl(r10,h0,l0); split_hl(r11,h1,l1);
            bh2a[kc] = packh(h0,h1); bl2a[kc] = packh(l0,l1);
            split_hl(r12,h0,l0); split_hl(r13,h1,l1);
            bh3a[kc] = packh(h0,h1); bl3a[kc] = packh(l0,l1);
        }

        #pragma unroll
        for (int nc = 0; nc < 8; nc++) {
            float b0 = fb[64 + nc * 8 + 2 * t], b1v = fb[64 + nc * 8 + 2 * t + 1];
            float c0 = b0, c1 = b1v, c2 = b0, c3 = b1v;
            #pragma unroll
            for (int kc = 0; kc < 4; kc++) {
                const __half* ph = smh + W2HI + (nc * 8 + g) * AST + kc * 16 + 2 * t;
                const __half* pl = smh + W2LO + (nc * 8 + g) * AST + kc * 16 + 2 * t;
                uint32_t wh0 = *(const uint32_t*)ph;
                uint32_t wh1 = *(const uint32_t*)(ph + 8);
                uint32_t wl0 = *(const uint32_t*)pl;
                uint32_t wl1 = *(const uint32_t*)(pl + 8);
                mma16816(c0,c1,c2,c3, bh0a[kc],bh1a[kc],bh2a[kc],bh3a[kc], wh0,wh1);
                mma16816(c0,c1,c2,c3, bl0a[kc],bl1a[kc],bl2a[kc],bl3a[kc], wh0,wh1);
                mma16816(c0,c1,c2,c3, bh0a[kc],bh1a[kc],bh2a[kc],bh3a[kc], wl0,wl1);
            }
            float f0 = fmaxf(c0, 0.f), f1 = fmaxf(c1, 0.f);
            float f2 = fmaxf(c2, 0.f), f3 = fmaxf(c3, 0.f);
            int col  = nc * 8 + 2 * t;
            int row0 = rowBase + g;
            int row1 = row0 + 8;
            if (row0 < n) {
                *(float2*)(xout + (size_t)row0 * DD + col) = make_float2(f0, f1);
                *(uint32_t*)(xh + (size_t)row0 * DD + col) = ph2(f0, f1);
            }
            if (row1 < n) {
                *(float2*)(xout + (size_t)row1 * DD + col) = make_float2(f2, f3);
                *(uint32_t*)(xh + (size_t)row1 * DD + col) = ph2(f2, f3);
            }
        }
    }
}

// ---------------------------------------------------------------------------
// Final projection on tensor cores: out = x @ Wf + bf (no relu), compensated.
// ---------------------------------------------------------------------------
#define FWHI  0
#define FWLO  4608
#define FA_HI 9216
#define FA_LO 18432
#define F_TOT 27648
#define FIN_SMEM_BYTES (F_TOT * 2 + 64 * 4)

__global__ void __launch_bounds__(256, 2) final_mma_kernel(
    const float* __restrict__ xin,
    const float* __restrict__ Wfg, const float* __restrict__ bfg,
    float* __restrict__ out, int n, int nTiles)
{
    extern __shared__ __half smh[];
    float* fb = (float*)(smh + F_TOT);
    const int tid  = threadIdx.x;
    const int warp = tid >> 5;
    const int lane = tid & 31;
    const int g    = lane >> 2;
    const int t    = lane & 3;

    for (int e = tid; e < 4096; e += 256) {
        int k = e >> 6, nn = e & 63;
        float w = __ldg(Wfg + e);
        __half h, lo;
        split_hl(w, h, lo);
        smh[FWHI + nn * AST + k] = h;  smh[FWLO + nn * AST + k] = lo;
    }
    if (tid < 64) fb[tid] = __ldg(bfg + tid);
    __syncthreads();

    __half* Ah = smh + FA_HI + warp * (16 * AST);
    __half* Al = smh + FA_LO + warp * (16 * AST);

    for (int tile = blockIdx.x; tile < nTiles; tile += gridDim.x) {
        const int rowBase = tile * 128 + warp * 16;

        __syncwarp();
        {
            const float4* gsrc = (const float4*)xin + (size_t)rowBase * 16;
            #pragma unroll
            for (int i = 0; i < 8; i++) {
                int idx = i * 32 + lane;
                float4 v = __ldg(gsrc + idx);
                int r = idx >> 4, c4 = idx & 15;
                __half h0,l0,h1,l1,h2v,l2,h3,l3;
                split_hl(v.x, h0, l0); split_hl(v.y, h1, l1);
                split_hl(v.z, h2v, l2); split_hl(v.w, h3, l3);
                uint2 hh; hh.x = packh(h0, h1); hh.y = packh(h2v, h3);
                uint2 ll; ll.x = packh(l0, l1); ll.y = packh(l2, l3);
                *(uint2*)(Ah + r * AST + c4 * 4) = hh;
                *(uint2*)(Al + r * AST + c4 * 4) = ll;
            }
        }
        __syncwarp();

        uint32_t ah0[4], ah1[4], ah2[4], ah3[4];
        uint32_t al0[4], al1[4], al2[4], al3[4];
        #pragma unroll
        for (int kc = 0; kc < 4; kc++) {
            int o0 = g * AST + kc * 16 + 2 * t;
            int o1 = (g + 8) * AST + kc * 16 + 2 * t;
            ah0[kc] = *(const uint32_t*)(Ah + o0);
            ah1[kc] = *(const uint32_t*)(Ah + o1);
            ah2[kc] = *(const uint32_t*)(Ah + o0 + 8);
            ah3[kc] = *(const uint32_t*)(Ah + o1 + 8);
            al0[kc] = *(const uint32_t*)(Al + o0);
            al1[kc] = *(const uint32_t*)(Al + o1);
            al2[kc] = *(const uint32_t*)(Al + o0 + 8);
            al3[kc] = *(const uint32_t*)(Al + o1 + 8);
        }

        #pragma unroll
        for (int nc = 0; nc < 8; nc++) {
            float b0 = fb[nc * 8 + 2 * t], b1v = fb[nc * 8 + 2 * t + 1];
            float c0 = b0, c1 = b1v, c2 = b0, c3 = b1v;
            #pragma unroll
            for (int kc = 0; kc < 4; kc++) {
                const __half* ph = smh + FWHI + (nc * 8 + g) * AST + kc * 16 + 2 * t;
                const __half* pl = smh + FWLO + (nc * 8 + g) * AST + kc * 16 + 2 * t;
                uint32_t bh0 = *(const uint32_t*)ph;
                uint32_t bh1 = *(const uint32_t*)(ph + 8);
                uint32_t bl0 = *(const uint32_t*)pl;
                uint32_t bl1 = *(const uint32_t*)(pl + 8);
                mma16816(c0,c1,c2,c3, ah0[kc],ah1[kc],ah2[kc],ah3[kc], bh0,bh1);
                mma16816(c0,c1,c2,c3, al0[kc],al1[kc],al2[kc],al3[kc], bh0,bh1);
                mma16816(c0,c1,c2,c3, ah0[kc],ah1[kc],ah2[kc],ah3[kc], bl0,bl1);
            }
            int col  = nc * 8 + 2 * t;
            int row0 = rowBase + g;
            int row1 = row0 + 8;
            if (row0 < n)
                *(float2*)(out + (size_t)row0 * DD + col) = make_float2(c0, c1);
            if (row1 < n)
                *(float2*)(out + (size_t)row1 * DD + col) = make_float2(c2, c3);
        }
    }
}

// ---------------------------------------------------------------------------
// Launch
// ---------------------------------------------------------------------------
extern "C" void kernel_launch(void* const* d_in, const int* in_sizes, int n_in,
                              void* d_out, int out_size)
{
    const float* x   = (const float*)d_in[0];
    const int*   ei  = (const int*)  d_in[1];
    const float* W1  = (const float*)d_in[2];
    const float* b1  = (const float*)d_in[3];
    const float* W2  = (const float*)d_in[4];
    const float* b2  = (const float*)d_in[5];
    const float* eps = (const float*)d_in[6];
    const float* Wf  = (const float*)d_in[7];
    const float* bf  = (const float*)d_in[8];

    const int n = in_sizes[0] / DD;
    const int E = in_sizes[1] / 2;
    const int* src = ei;
    const int* dst = ei + E;

    float *bufA, *bufB, *hin;
    __half* xh;
    int *off, *cur, *csr;
    cudaGetSymbolAddress((void**)&bufA, g_bufA);
    cudaGetSymbolAddress((void**)&bufB, g_bufB);
    cudaGetSymbolAddress((void**)&hin,  g_hin);
    cudaGetSymbolAddress((void**)&xh,   g_xh);
    cudaGetSymbolAddress((void**)&off,  g_off);
    cudaGetSymbolAddress((void**)&cur,  g_cur);
    cudaGetSymbolAddress((void**)&csr,  g_csr);

    cudaFuncSetAttribute(gin_mlp_kernel,
                         cudaFuncAttributeMaxDynamicSharedMemorySize,
                         MLP_SMEM_BYTES);
    cudaFuncSetAttribute(final_mma_kernel,
                         cudaFuncAttributeMaxDynamicSharedMemorySize,
                         FIN_SMEM_BYTES);

    // ---- CSR build + fp16 mirror of x (cur zero on entry; restored at end)
    const int eQuads = (E + 3) / 4;
    hist_kernel<<<(eQuads + 255) / 256, 256>>>(dst, E, cur);
    x2h_kernel<<<(n * 16 + 255) / 256, 256>>>(x, xh, n * 16);
    scan_one_kernel<<<(n + 255) / 256, 256>>>(cur, off, n, E);
    fill_kernel<<<(eQuads + 255) / 256, 256>>>(src, dst, E, cur, csr);

    // ---- Layers
    const int gatherBlocks = (n * 8 + 255) / 256;
    const int mlpTiles = (n + 127) / 128;
    int mlpGrid = 296;                        // 2 blocks x 148 SMs
    if (mlpGrid > mlpTiles) mlpGrid = mlpTiles;

    const float* curx = x;
    float*       nxt  = bufA;
    for (int l = 0; l < 3; l++) {
        gather_kernel<<<gatherBlocks, 256>>>(curx, xh, off, csr, eps, l, hin, n);
        gin_mlp_kernel<<<mlpGrid, 256, MLP_SMEM_BYTES>>>(
            hin, W1, b1, W2, b2, l, nxt, xh, n, mlpTiles);
        curx = nxt;
        nxt = (curx == bufA) ? bufB : bufA;
    }

    final_mma_kernel<<<mlpGrid, 256, FIN_SMEM_BYTES>>>(
        curx, Wf, bf, (float*)d_out, n, mlpTiles);

    // ---- restore cur = 0 for the next call
    zero_cur_kernel<<<(n + 255) / 256, 256>>>(cur, n);
}